// round 2
// baseline (speedup 1.0000x reference)
#include <cuda_runtime.h>
#include <math.h>

// Problem constants (fixed shapes from reference)
#define B_ 16
#define C_ 256
#define H_ 128
#define W_ 128
#define PLANE (H_ * W_)          // 16384 elements per (b,c) plane
#define NPLANES (B_ * C_)        // 4096
#define DIMH 128                 // dim/2

// Scratch: pooled means and final per-plane scale
__device__ float g_pooled[NPLANES];
__device__ float g_scale[NPLANES];

// ---------------------------------------------------------------------------
// Kernel 1: per-plane mean. One block per (b,c) plane; plane is contiguous.
// 256 threads x 16 float4 loads each = 16384 floats.
// ---------------------------------------------------------------------------
__global__ __launch_bounds__(256) void pool_kernel(const float* __restrict__ x) {
    const int plane = blockIdx.x;
    const float4* __restrict__ p = reinterpret_cast<const float4*>(x) + (size_t)plane * (PLANE / 4);
    const int t = threadIdx.x;

    float acc = 0.f;
#pragma unroll
    for (int k = 0; k < PLANE / 4 / 256; ++k) {
        float4 v = p[t + k * 256];
        acc += (v.x + v.y) + (v.z + v.w);
    }
    // warp reduce
#pragma unroll
    for (int off = 16; off > 0; off >>= 1)
        acc += __shfl_xor_sync(0xFFFFFFFFu, acc, off);

    __shared__ float warp_sums[8];
    if ((t & 31) == 0) warp_sums[t >> 5] = acc;
    __syncthreads();
    if (t == 0) {
        float s = 0.f;
#pragma unroll
        for (int w = 0; w < 8; ++w) s += warp_sums[w];
        g_pooled[plane] = s * (1.0f / PLANE);
    }
}

// ---------------------------------------------------------------------------
// Kernel 2: tiny MLP + gate. One block per batch b (16 blocks, 256 threads).
//   h    = relu(pooled @ W1^T + b1)           (128)
//   wgt  = sigmoid(h @ W2^T + b2)             (256)
//   gate = sigmoid(pooled @ Wc^T + bc)        (256)
//   scale = wgt + gate
// ---------------------------------------------------------------------------
__device__ __forceinline__ float sigmoidf_(float v) {
    return 1.0f / (1.0f + expf(-v));
}

__global__ __launch_bounds__(256) void mlp_kernel(
    const float* __restrict__ W1, const float* __restrict__ b1,
    const float* __restrict__ W2, const float* __restrict__ b2,
    const float* __restrict__ Wc, const float* __restrict__ bc) {
    const int b = blockIdx.x;
    const int t = threadIdx.x;

    __shared__ float sp[C_];    // pooled for this batch
    __shared__ float sh[DIMH];  // hidden

    sp[t] = g_pooled[b * C_ + t];
    __syncthreads();

    if (t < DIMH) {
        float acc = b1[t];
        const float* __restrict__ row = W1 + t * C_;
#pragma unroll 8
        for (int c = 0; c < C_; ++c) acc = fmaf(sp[c], row[c], acc);
        sh[t] = fmaxf(acc, 0.0f);
    }
    __syncthreads();

    // weight branch
    float accw = b2[t];
    {
        const float* __restrict__ row = W2 + t * DIMH;
#pragma unroll 8
        for (int j = 0; j < DIMH; ++j) accw = fmaf(sh[j], row[j], accw);
    }
    // gate branch
    float accg = bc[t];
    {
        const float* __restrict__ row = Wc + t * C_;
#pragma unroll 8
        for (int k = 0; k < C_; ++k) accg = fmaf(sp[k], row[k], accg);
    }
    g_scale[b * C_ + t] = sigmoidf_(accw) + sigmoidf_(accg);
}

// ---------------------------------------------------------------------------
// Kernel 3: out = x * scale[plane]. One block per plane, float4, coalesced.
// ---------------------------------------------------------------------------
__global__ __launch_bounds__(256) void scale_kernel(const float* __restrict__ x,
                                                    float* __restrict__ out) {
    const int plane = blockIdx.x;
    const float s = __ldg(&g_scale[plane]);
    const float4* __restrict__ pin = reinterpret_cast<const float4*>(x) + (size_t)plane * (PLANE / 4);
    float4* __restrict__ pout = reinterpret_cast<float4*>(out) + (size_t)plane * (PLANE / 4);
    const int t = threadIdx.x;

#pragma unroll
    for (int k = 0; k < PLANE / 4 / 256; ++k) {
        float4 v = pin[t + k * 256];
        v.x *= s; v.y *= s; v.z *= s; v.w *= s;
        pout[t + k * 256] = v;
    }
}

// ---------------------------------------------------------------------------
extern "C" void kernel_launch(void* const* d_in, const int* in_sizes, int n_in,
                              void* d_out, int out_size) {
    const float* x  = (const float*)d_in[0];
    const float* W1 = (const float*)d_in[1];
    const float* b1 = (const float*)d_in[2];
    const float* W2 = (const float*)d_in[3];
    const float* b2 = (const float*)d_in[4];
    const float* Wc = (const float*)d_in[5];
    const float* bc = (const float*)d_in[6];
    float* out = (float*)d_out;

    pool_kernel<<<NPLANES, 256>>>(x);
    mlp_kernel<<<B_, 256>>>(W1, b1, W2, b2, Wc, bc);
    scale_kernel<<<NPLANES, 256>>>(x, out);
}

// round 3
// speedup vs baseline: 1.4693x; 1.4693x over previous
#include <cuda_runtime.h>
#include <math.h>

#define B_ 16
#define C_ 256
#define H_ 128
#define W_ 128
#define PLANE (H_ * W_)          // 16384 elements per (b,c) plane
#define NPLANES (B_ * C_)        // 4096
#define DIMH 128                 // dim/2

__device__ float g_pooled[NPLANES];
__device__ float g_scale[NPLANES];

// ---------------------------------------------------------------------------
// Kernel 1: per-plane mean. One block per (b,c) plane (contiguous planes).
// Achieves 6.47 TB/s (80.9% spec) — leave as is.
// ---------------------------------------------------------------------------
__global__ __launch_bounds__(256) void pool_kernel(const float* __restrict__ x) {
    const int plane = blockIdx.x;
    const float4* __restrict__ p = reinterpret_cast<const float4*>(x) + (size_t)plane * (PLANE / 4);
    const int t = threadIdx.x;

    float acc = 0.f;
#pragma unroll
    for (int k = 0; k < PLANE / 4 / 256; ++k) {
        float4 v = p[t + k * 256];
        acc += (v.x + v.y) + (v.z + v.w);
    }
#pragma unroll
    for (int off = 16; off > 0; off >>= 1)
        acc += __shfl_xor_sync(0xFFFFFFFFu, acc, off);

    __shared__ float warp_sums[8];
    if ((t & 31) == 0) warp_sums[t >> 5] = acc;
    __syncthreads();
    if (t == 0) {
        float s = 0.f;
#pragma unroll
        for (int w = 0; w < 8; ++w) s += warp_sums[w];
        g_pooled[plane] = s * (1.0f / PLANE);
    }
}

// ---------------------------------------------------------------------------
// Kernel 2: tiny MLP + gate, warp-dot formulation with COALESCED weight loads.
// grid (B_=16, 8): blockIdx.y picks a 32-wide output chunk; hidden layer is
// recomputed per block (cheap, L2-hot weights). 128 blocks total.
// ---------------------------------------------------------------------------
__device__ __forceinline__ float sigmoidf_(float v) {
    return 1.0f / (1.0f + expf(-v));
}

__device__ __forceinline__ float warp_sum(float v) {
#pragma unroll
    for (int off = 16; off > 0; off >>= 1)
        v += __shfl_xor_sync(0xFFFFFFFFu, v, off);
    return v;
}

__global__ __launch_bounds__(256) void mlp_kernel(
    const float* __restrict__ W1, const float* __restrict__ b1,
    const float* __restrict__ W2, const float* __restrict__ b2,
    const float* __restrict__ Wc, const float* __restrict__ bc) {
    const int b    = blockIdx.x;
    const int t    = threadIdx.x;
    const int wid  = t >> 5;
    const int lane = t & 31;

    __shared__ float sp[C_];
    __shared__ float sh[DIMH];

    sp[t] = g_pooled[b * C_ + t];
    __syncthreads();

    // Hidden layer: 128 outputs, 8 warps x 16 outputs. Lanes sweep input dim
    // (coalesced within the warp), shuffle-reduce.
#pragma unroll
    for (int i = 0; i < DIMH / (8 * 1); i += 1) {   // 16 outputs per warp
        const int o = wid * 16 + i;
        const float* __restrict__ row = W1 + o * C_;
        float acc = 0.f;
#pragma unroll
        for (int k = 0; k < C_ / 32; ++k)
            acc = fmaf(sp[lane + 32 * k], row[lane + 32 * k], acc);
        acc = warp_sum(acc);
        if (lane == 0) sh[o] = fmaxf(acc + b1[o], 0.0f);
    }
    __syncthreads();

    // Output chunk: 32 outputs for this block; each warp computes 4.
    const int obase = blockIdx.y * 32 + wid * 4;
#pragma unroll
    for (int i = 0; i < 4; ++i) {
        const int o = obase + i;

        const float* __restrict__ row2 = W2 + o * DIMH;
        float accw = 0.f;
#pragma unroll
        for (int k = 0; k < DIMH / 32; ++k)
            accw = fmaf(sh[lane + 32 * k], row2[lane + 32 * k], accw);

        const float* __restrict__ rowc = Wc + o * C_;
        float accg = 0.f;
#pragma unroll
        for (int k = 0; k < C_ / 32; ++k)
            accg = fmaf(sp[lane + 32 * k], rowc[lane + 32 * k], accg);

        accw = warp_sum(accw);
        accg = warp_sum(accg);
        if (lane == 0)
            g_scale[b * C_ + o] = sigmoidf_(accw + b2[o]) + sigmoidf_(accg + bc[o]);
    }
}

// ---------------------------------------------------------------------------
// Kernel 3: out = x * scale[plane]. REVERSED plane order: pool streamed x
// front-to-back, so the tail of x (~120 MB) is still L2-resident; walking
// back-to-front converts those reads into L2 hits. Streaming stores keep
// out from evicting that residue.
// ---------------------------------------------------------------------------
__global__ __launch_bounds__(256) void scale_kernel(const float* __restrict__ x,
                                                    float* __restrict__ out) {
    const int plane = NPLANES - 1 - blockIdx.x;
    const float s = g_scale[plane];
    const float4* __restrict__ pin = reinterpret_cast<const float4*>(x) + (size_t)plane * (PLANE / 4);
    float4* __restrict__ pout = reinterpret_cast<float4*>(out) + (size_t)plane * (PLANE / 4);
    const int t = threadIdx.x;

#pragma unroll
    for (int k = 0; k < PLANE / 4 / 256; ++k) {
        float4 v = pin[t + k * 256];
        v.x *= s; v.y *= s; v.z *= s; v.w *= s;
        __stcs(&pout[t + k * 256], v);
    }
}

// ---------------------------------------------------------------------------
extern "C" void kernel_launch(void* const* d_in, const int* in_sizes, int n_in,
                              void* d_out, int out_size) {
    const float* x  = (const float*)d_in[0];
    const float* W1 = (const float*)d_in[1];
    const float* b1 = (const float*)d_in[2];
    const float* W2 = (const float*)d_in[3];
    const float* b2 = (const float*)d_in[4];
    const float* Wc = (const float*)d_in[5];
    const float* bc = (const float*)d_in[6];
    float* out = (float*)d_out;

    pool_kernel<<<NPLANES, 256>>>(x);
    mlp_kernel<<<dim3(B_, 8), 256>>>(W1, b1, W2, b2, Wc, bc);
    scale_kernel<<<NPLANES, 256>>>(x, out);
}